// round 14
// baseline (speedup 1.0000x reference)
#include <cuda_runtime.h>
#include <cstdint>

// ChamferDistance on GB300 — Round 14: exact NN, warp-granular pruned scan.
// Stage 1: counting-sort both sets by z into 256 buckets (SoA + orig idx),
//          512 threads per (set,batch) CTA.
// Stage 2: ONE WARP PER CTA (2048 CTAs). Each warp owns 64 contiguous sorted
//          queries (QP=2), stages 64-ref tiles into warp-private smem with
//          coalesced LDG.128 prefetch, runs the validated broadcast-LDS
//          f32x2-FFMA inner loop, and expands its z-window with per-query
//          union bounds (SHFL only). Exact; each output written once.

#define NB    256
#define ST    512
#define QP    2
#define WQ    (32 * QP)    // 64 queries per warp
#define TW    64           // refs per tile (1KB smem)
#define BSTEP 2
#define PAD   2
#define MAXP  8192
#define MAXB  8

__device__ float g_sx [2][MAXB * MAXP];
__device__ float g_sy [2][MAXB * MAXP];
__device__ float g_sz [2][MAXB * MAXP];
__device__ float g_sq [2][MAXB * MAXP];
__device__ int   g_idx[2][MAXB * MAXP];
__device__ int   g_off[2][MAXB][NB + 1];
__device__ float g_zmin[2][MAXB];
__device__ float g_w   [2][MAXB];
__device__ float g_invw[2][MAXB];

// ---------------- Stage 1: z counting sort (SoA output) ----------------
__global__ __launch_bounds__(ST)
void cd_bucket_kernel(const float* __restrict__ xyz1,
                      const float* __restrict__ xyz2,
                      int Npts)
{
    const int set = blockIdx.y;
    const int b   = blockIdx.x;
    const float* __restrict__ src =
        ((set == 0) ? xyz1 : xyz2) + (size_t)b * Npts * 3;
    const int tid = threadIdx.x;

    __shared__ float s_red[ST];
    __shared__ int   s_hist[NB];
    __shared__ int   s_off[NB + 1];
    __shared__ int   s_cur[NB];
    __shared__ float s_zmin, s_invw;

    float zmn = 3.402823466e+38f, zmx = -3.402823466e+38f;
    for (int j = tid; j < Npts; j += ST) {
        float z = src[j * 3 + 2];
        zmn = fminf(zmn, z);
        zmx = fmaxf(zmx, z);
    }
    s_red[tid] = zmn; __syncthreads();
    for (int s = ST / 2; s > 0; s >>= 1) {
        if (tid < s) s_red[tid] = fminf(s_red[tid], s_red[tid + s]);
        __syncthreads();
    }
    float zlo = s_red[0]; __syncthreads();
    s_red[tid] = zmx; __syncthreads();
    for (int s = ST / 2; s > 0; s >>= 1) {
        if (tid < s) s_red[tid] = fmaxf(s_red[tid], s_red[tid + s]);
        __syncthreads();
    }
    if (tid == 0) {
        float zhi = s_red[0];
        float w = (zhi - zlo) / NB;
        if (!(w > 0.f)) w = 1e-30f;
        s_zmin = zlo;
        s_invw = 1.0f / w;
        g_zmin[set][b] = zlo;
        g_w[set][b]    = w;
        g_invw[set][b] = 1.0f / w;
    }
    if (tid < NB) s_hist[tid] = 0;
    __syncthreads();

    for (int j = tid; j < Npts; j += ST) {
        float z = src[j * 3 + 2];
        int bb = min(NB - 1, max(0, (int)((z - s_zmin) * s_invw)));
        atomicAdd(&s_hist[bb], 1);
    }
    __syncthreads();
    if (tid == 0) {
        int acc = 0;
        for (int i = 0; i < NB; i++) { s_off[i] = acc; acc += s_hist[i]; }
        s_off[NB] = acc;
    }
    __syncthreads();
    if (tid < NB) s_cur[tid] = s_off[tid];
    if (tid < NB) g_off[set][b][tid] = s_off[tid];
    if (tid == 0) g_off[set][b][NB] = s_off[NB];
    __syncthreads();

    const size_t bo = (size_t)b * Npts;
    for (int j = tid; j < Npts; j += ST) {
        float x = src[j * 3 + 0];
        float y = src[j * 3 + 1];
        float z = src[j * 3 + 2];
        int bb = min(NB - 1, max(0, (int)((z - s_zmin) * s_invw)));
        int pos = atomicAdd(&s_cur[bb], 1);
        g_sx[set][bo + pos] = x;
        g_sy[set][bo + pos] = y;
        g_sz[set][bo + pos] = z;
        g_sq[set][bo + pos] = fmaf(x, x, fmaf(y, y, z * z));
        g_idx[set][bo + pos] = j;
    }
}

// ---------------- helpers ----------------
__device__ __forceinline__ uint64_t cd_dup2(float v) {
    uint64_t r;
    asm("mov.b64 %0, {%1, %1};" : "=l"(r) : "r"(__float_as_uint(v)));
    return r;
}

__device__ __forceinline__ void cd_dot2(uint64_t qx, uint64_t qy, uint64_t qz,
                                        uint64_t px, uint64_t py, uint64_t pz,
                                        uint64_t s,
                                        float& dlo, float& dhi) {
    uint32_t lo, hi;
    asm("{\n\t"
        ".reg .b64 t;\n\t"
        "fma.rn.f32x2 t, %2, %3, %4;\n\t"
        "fma.rn.f32x2 t, %5, %6, t;\n\t"
        "fma.rn.f32x2 t, %7, %8, t;\n\t"
        "mov.b64 {%0, %1}, t;\n\t"
        "}"
        : "=r"(lo), "=r"(hi)
        : "l"(qz), "l"(pz), "l"(s),
          "l"(qy), "l"(py),
          "l"(qx), "l"(px));
    dlo = __uint_as_float(lo);
    dhi = __uint_as_float(hi);
}

__device__ __forceinline__ float wmax(float v) {
    #pragma unroll
    for (int o = 16; o; o >>= 1) v = fmaxf(v, __shfl_xor_sync(0xFFFFFFFFu, v, o));
    return v;
}
__device__ __forceinline__ float wmin(float v) {
    #pragma unroll
    for (int o = 16; o; o >>= 1) v = fminf(v, __shfl_xor_sync(0xFFFFFFFFu, v, o));
    return v;
}

// ---------------- Stage 2: warp-granular pruned NN (32 thr/CTA) ----------
__global__ __launch_bounds__(32, 16)
void cd_nn_kernel(float* __restrict__ out, int Npts, int B)
{
    const int dir  = blockIdx.z;
    const int b    = blockIdx.y;
    const int qset = dir, rset = 1 - dir;
    const int lane = threadIdx.x;

    const size_t qo = (size_t)b * Npts;
    const float* __restrict__ QX = &g_sx[qset][qo];
    const float* __restrict__ QY = &g_sy[qset][qo];
    const float* __restrict__ QZ = &g_sz[qset][qo];
    const float* __restrict__ QS = &g_sq[qset][qo];
    const int*   __restrict__ QI = &g_idx[qset][qo];

    const float4* __restrict__ RX4 = (const float4*)&g_sx[rset][qo];
    const float4* __restrict__ RY4 = (const float4*)&g_sy[rset][qo];
    const float4* __restrict__ RZ4 = (const float4*)&g_sz[rset][qo];
    const float4* __restrict__ RQ4 = (const float4*)&g_sq[rset][qo];
    const int* __restrict__ off = g_off[rset][b];
    const float zminR = g_zmin[rset][b];
    const float wR    = g_w[rset][b];
    const float invwR = g_invw[rset][b];

    // Warp-private staging buffer: [arr*TW + i], arrs = x,y,z,sq
    __shared__ __align__(16) float sw[4 * TW];

    const int qbase = blockIdx.x * WQ;

    uint64_t qxd[QP], qyd[QP], qzd[QP];
    float qsq[QP], zq[QP], me[QP];
    int qidx[QP];
    #pragma unroll
    for (int p = 0; p < QP; p++) {
        int ii = qbase + p * 32 + lane;
        qidx[p] = ii;
        float x = QX[ii], y = QY[ii], z = QZ[ii];
        qxd[p] = cd_dup2(-2.0f * x);
        qyd[p] = cd_dup2(-2.0f * y);
        qzd[p] = cd_dup2(-2.0f * z);
        qsq[p] = QS[ii];
        zq[p]  = z;
        me[p]  = 3.402823466e+38f;
    }

    float zqmin = wmin(fminf(zq[0], zq[1]));
    float zqmax = wmax(fmaxf(zq[0], zq[1]));

    // Staging roles: lanes 0-15 load x+z chunks, lanes 16-31 load y+sq.
    const int k4 = (lane & 15) << 2;
    const int hi = lane >> 4;
    const float4* __restrict__ SA = hi ? RY4 : RX4;
    const float4* __restrict__ SB = hi ? RQ4 : RZ4;
    const float padB = hi ? 3.402823466e+38f : 0.0f;

    float4 ra, rb;

    auto ldtile = [&](int jt, int j1a) {
        int idx = jt + k4;
        if (idx < j1a) {
            ra = SA[idx >> 2];
            rb = SB[idx >> 2];
        } else {
            ra = make_float4(0.f, 0.f, 0.f, 0.f);
            rb = make_float4(padB, padB, padB, padB);
        }
    };

    auto scan = [&](int j0, int j1) {
        j0 &= ~3;
        j1 = min((j1 + 3) & ~3, Npts);
        if (j0 >= j1) return;
        ldtile(j0, j1);
        for (int jt = j0; jt < j1; jt += TW) {
            __syncwarp();
            *(float4*)&sw[hi * TW + k4]       = ra;
            *(float4*)&sw[(2 + hi) * TW + k4] = rb;
            __syncwarp();
            int nx = jt + TW;
            if (nx < j1) ldtile(nx, j1);
            const uint64_t* __restrict__ px2 = (const uint64_t*)&sw[0];
            const uint64_t* __restrict__ py2 = (const uint64_t*)&sw[TW];
            const uint64_t* __restrict__ pz2 = (const uint64_t*)&sw[2 * TW];
            const uint64_t* __restrict__ ps2 = (const uint64_t*)&sw[3 * TW];
            #pragma unroll 4
            for (int jj = 0; jj < TW / 2; jj++) {
                uint64_t px = px2[jj], py = py2[jj];
                uint64_t pz = pz2[jj], ps = ps2[jj];
                #pragma unroll
                for (int p = 0; p < QP; p++) {
                    float dlo, dhi2;
                    cd_dot2(qxd[p], qyd[p], qzd[p], px, py, pz, ps, dlo, dhi2);
                    me[p] = fminf(me[p], fminf(dlo, dhi2));
                }
            }
        }
        __syncwarp();
    };

    int bq_lo = min(NB - 1, max(0, (int)((zqmin - zminR) * invwR)));
    int bq_hi = min(NB - 1, max(0, (int)((zqmax - zminR) * invwR)));
    int blo = max(bq_lo - PAD, 0);
    int bhi = min(bq_hi + 1 + PAD, NB);
    scan(off[blo], off[bhi]);

    for (;;) {
        float r0 = sqrtf(fmaxf(me[0] + qsq[0], 0.0f));
        float r1 = sqrtf(fmaxf(me[1] + qsq[1], 0.0f));
        float hi_need = wmax(fmaxf(zq[0] + r0, zq[1] + r1));
        float lo_need = wmin(fminf(zq[0] - r0, zq[1] - r1));

        bool okLo = (blo > 0)  && (zminR + (float)blo * wR > lo_need);
        bool okHi = (bhi < NB) && (zminR + (float)bhi * wR < hi_need);
        if (!okLo && !okHi) break;
        if (okLo) {
            int nlo = max(blo - BSTEP, 0);
            scan(off[nlo], off[blo]);
            blo = nlo;
        }
        if (okHi) {
            int nhi = min(bhi + BSTEP, NB);
            scan(off[bhi], off[nhi]);
            bhi = nhi;
        }
    }

    float* __restrict__ o = out + ((dir == 0) ? 0 : (size_t)B * Npts)
                          + (size_t)b * Npts;
    #pragma unroll
    for (int p = 0; p < QP; p++) {
        float d = fmaxf(me[p] + qsq[p], 0.0f);
        o[QI[qidx[p]]] = d;
    }
}

extern "C" void kernel_launch(void* const* d_in, const int* in_sizes, int n_in,
                              void* d_out, int out_size)
{
    const float* xyz1 = (const float*)d_in[0];
    const float* xyz2 = (const float*)d_in[1];
    float* out = (float*)d_out;

    const int B = 8;
    const int N = (in_sizes[0] / 3) / B;   // 8192 (== M)

    {
        dim3 grid(B, 2);
        cd_bucket_kernel<<<grid, ST>>>(xyz1, xyz2, N);
    }
    {
        int qblocks = N / WQ;                 // 128 warps per (b,dir)
        dim3 grid(qblocks, B, 2);             // 128 x 8 x 2 = 2048 CTAs
        cd_nn_kernel<<<grid, 32>>>(out, N, B);
    }
}